// round 1
// baseline (speedup 1.0000x reference)
#include <cuda_runtime.h>

// ---------------- problem dims ----------------
constexpr int B = 2, D1 = 8, D2 = 16, D3 = 32, D4 = 32, F = 8, H = 16, H2 = 32;
constexpr int NV = B * D1 * D2 * D3 * D4;  // 262144 voxels
constexpr float LRELU = 0.01f;

// ---------------- static scratch (no allocation allowed) ----------------
__device__ float g_bufA[NV * H];     // embed out / conv3 out
__device__ float g_bufB[NV * H];     // conv1 out
__device__ float g_bufC[NV * H2];    // conv2 out
__device__ float g_W1t[625 * H * H];
__device__ float g_W2t[625 * H * H2];
__device__ float g_W3t[625 * H2 * H];
__device__ double g_sum[3 * 32];
__device__ double g_ssq[3 * 32];

// ---------------- small kernels ----------------
__global__ void zero_stats_kernel(double* s, double* q) {
    int i = threadIdx.x;
    if (i < 96) { s[i] = 0.0; q[i] = 0.0; }
}

// W[cout][cin][625] -> Wt[tap][cin][cout]
__global__ void reorder_w_kernel(const float* __restrict__ src, float* __restrict__ dst,
                                 int CIN, int COUT) {
    int n = 625 * CIN * COUT;
    int i = blockIdx.x * blockDim.x + threadIdx.x;
    if (i >= n) return;
    int co  = i % COUT;
    int ci  = (i / COUT) % CIN;
    int tap = i / (COUT * CIN);
    dst[i] = src[(co * CIN + ci) * 625 + tap];
}

// h[v][h16] = x[v][f8] @ w_emb[f][h] + b_emb
__global__ void embed_kernel(const float* __restrict__ x, const float* __restrict__ we,
                             const float* __restrict__ be, float* __restrict__ out) {
    __shared__ float sw[F * H];
    __shared__ float sb[H];
    if (threadIdx.x < F * H) sw[threadIdx.x] = we[threadIdx.x];
    if (threadIdx.x < H) sb[threadIdx.x] = be[threadIdx.x];
    __syncthreads();
    int v = blockIdx.x * blockDim.x + threadIdx.x;
    if (v >= NV) return;
    float xf[F];
    const float4* xp = (const float4*)(x + v * F);
    float4 x0 = xp[0], x1 = xp[1];
    xf[0]=x0.x; xf[1]=x0.y; xf[2]=x0.z; xf[3]=x0.w;
    xf[4]=x1.x; xf[5]=x1.y; xf[6]=x1.z; xf[7]=x1.w;
    float o[H];
#pragma unroll
    for (int h = 0; h < H; h++) {
        float a = sb[h];
#pragma unroll
        for (int f = 0; f < F; f++) a += xf[f] * sw[f * H + h];
        o[h] = a;
    }
    float4* op = (float4*)(out + v * H);
#pragma unroll
    for (int k = 0; k < 4; k++) op[k] = make_float4(o[4*k], o[4*k+1], o[4*k+2], o[4*k+3]);
}

// ---------------- 4D conv ----------------
// block covers (b, d1, d2, 8 consecutive d3 rows) x all d4 -> M = 256 voxels
// thread tile: 8 m (d3 rows) x 4 cout.  in/out channel-last.
template <int CIN, int COUT>
__global__ void __launch_bounds__(32 * (COUT / 4))
conv4d_kernel(const float* __restrict__ in, const float* __restrict__ wt,
              const float* __restrict__ bias, float* __restrict__ out) {
    constexpr int NT   = COUT / 4;
    constexpr int NTHR = 32 * NT;
    constexpr int C4   = CIN / 4;
    constexpr int ROWS = 12;   // 8 out rows + halo 2 each side
    constexpr int D4P  = 36;   // 32 + pad 2 each side
    constexpr int SIN4 = ROWS * C4 * D4P;        // float4 count
    constexpr int SW4  = 25 * CIN * COUT / 4;    // float4 count

    extern __shared__ float4 smem4[];
    float4* s_in = smem4;          // [row][c4][d4p]
    float4* s_w  = smem4 + SIN4;   // [dydx][cin][cout/4]

    int bi  = blockIdx.x;
    int d3b = (bi & 3) << 3;
    int d2  = (bi >> 2) & 15;
    int d1  = (bi >> 6) & 7;
    int b   = bi >> 9;

    int tid = threadIdx.x;
    int nt  = tid % NT;
    int d4  = tid / NT;  // 0..31

    float4 acc[8];
#pragma unroll
    for (int j = 0; j < 8; j++) acc[j] = make_float4(0.f, 0.f, 0.f, 0.f);

    const float4* wt4 = (const float4*)wt;

    for (int dt = 0; dt < 5; dt++) {
        int d1s = d1 + dt - 2;
        for (int dz = 0; dz < 5; dz++) {
            int d2s = d2 + dz - 2;
            bool v12 = ((unsigned)d1s < (unsigned)D1) && ((unsigned)d2s < (unsigned)D2);
            __syncthreads();
            // stage 12 input rows (zero padded)
            for (int i = tid; i < SIN4; i += NTHR) {
                int c4   = i % C4;
                int rest = i / C4;
                int d4p  = rest % D4P;
                int r    = rest / D4P;
                int d3s  = d3b + r - 2;
                float4 val = make_float4(0.f, 0.f, 0.f, 0.f);
                if (v12 && (unsigned)d3s < (unsigned)D3 && d4p >= 2 && d4p < 34) {
                    val = ((const float4*)(in +
                          (size_t)((((b * D1 + d1s) * D2 + d2s) * D3 + d3s) * D4 + (d4p - 2)) * CIN))[c4];
                }
                s_in[(r * C4 + c4) * D4P + d4p] = val;
            }
            // stage weight slice for (dt,dz): contiguous
            {
                const float4* wsrc = wt4 + (dt * 5 + dz) * SW4;
                for (int i = tid; i < SW4; i += NTHR) s_w[i] = wsrc[i];
            }
            __syncthreads();

#pragma unroll 1
            for (int dy = 0; dy < 5; dy++) {
#pragma unroll 1
                for (int dx = 0; dx < 5; dx++) {
#pragma unroll
                    for (int c4 = 0; c4 < C4; c4++) {
                        float4 bw[4];
                        int wbase = ((dy * 5 + dx) * CIN + c4 * 4) * NT + nt;
#pragma unroll
                        for (int jj = 0; jj < 4; jj++) bw[jj] = s_w[wbase + jj * NT];
#pragma unroll
                        for (int j = 0; j < 8; j++) {
                            float4 a = s_in[((j + dy) * C4 + c4) * D4P + d4 + dx];
                            acc[j].x += a.x * bw[0].x; acc[j].y += a.x * bw[0].y;
                            acc[j].z += a.x * bw[0].z; acc[j].w += a.x * bw[0].w;
                            acc[j].x += a.y * bw[1].x; acc[j].y += a.y * bw[1].y;
                            acc[j].z += a.y * bw[1].z; acc[j].w += a.y * bw[1].w;
                            acc[j].x += a.z * bw[2].x; acc[j].y += a.z * bw[2].y;
                            acc[j].z += a.z * bw[2].z; acc[j].w += a.z * bw[2].w;
                            acc[j].x += a.w * bw[3].x; acc[j].y += a.w * bw[3].y;
                            acc[j].z += a.w * bw[3].z; acc[j].w += a.w * bw[3].w;
                        }
                    }
                }
            }
        }
    }

    float4 bb = ((const float4*)bias)[nt];
#pragma unroll
    for (int j = 0; j < 8; j++) {
        int d3 = d3b + j;
        float4 r = acc[j];
        r.x += bb.x; r.y += bb.y; r.z += bb.z; r.w += bb.w;
        ((float4*)(out + (size_t)((((b * D1 + d1) * D2 + d2) * D3 + d3) * D4 + d4) * COUT))[nt] = r;
    }
}

// ---------------- batchnorm ----------------
template <int C>
__global__ void bn_stats_kernel(const float* __restrict__ buf, double* __restrict__ sum,
                                double* __restrict__ ssq) {
    __shared__ float s_s[C], s_q[C];
    int tid = threadIdx.x;
    if (tid < C) { s_s[tid] = 0.f; s_q[tid] = 0.f; }
    __syncthreads();
    int gid    = blockIdx.x * blockDim.x + tid;
    int stride = gridDim.x * blockDim.x;  // multiple of 32
    int ch     = gid % C;                 // constant per thread
    float ls = 0.f, lq = 0.f;
    for (int i = gid; i < NV * C; i += stride) {
        float v = buf[i];
        ls += v;
        lq += v * v;
    }
    atomicAdd(&s_s[ch], ls);
    atomicAdd(&s_q[ch], lq);
    __syncthreads();
    if (tid < C) {
        atomicAdd(&sum[tid], (double)s_s[tid]);
        atomicAdd(&ssq[tid], (double)s_q[tid]);
    }
}

template <int C>
__global__ void bn_apply_kernel(float* __restrict__ buf, const double* __restrict__ sum,
                                const double* __restrict__ ssq, const float* __restrict__ gamma,
                                const float* __restrict__ beta) {
    __shared__ float sc[C], sh[C];
    int tid = threadIdx.x;
    if (tid < C) {
        double m   = sum[tid] / (double)NV;
        double var = ssq[tid] / (double)NV - m * m;
        double inv = 1.0 / sqrt(var + 1e-5);
        float s = gamma[tid] * (float)inv;
        sc[tid] = s;
        sh[tid] = beta[tid] - (float)m * s;
    }
    __syncthreads();
    int gid    = blockIdx.x * blockDim.x + tid;
    int stride = gridDim.x * blockDim.x;
    float4* b4 = (float4*)buf;
    for (int i = gid; i < NV * C / 4; i += stride) {
        float4 v = b4[i];
        int c0 = (i * 4) % C;
        v.x = v.x * sc[c0]     + sh[c0];
        v.y = v.y * sc[c0 + 1] + sh[c0 + 1];
        v.z = v.z * sc[c0 + 2] + sh[c0 + 2];
        v.w = v.w * sc[c0 + 3] + sh[c0 + 3];
        v.x = fmaxf(v.x, LRELU * v.x);
        v.y = fmaxf(v.y, LRELU * v.y);
        v.z = fmaxf(v.z, LRELU * v.z);
        v.w = fmaxf(v.w, LRELU * v.w);
        b4[i] = v;
    }
}

// ---------------- projection ----------------
__global__ void proj_kernel(const float* __restrict__ buf, const float* __restrict__ wp,
                            const float* __restrict__ bp, float* __restrict__ out) {
    __shared__ float sw[H];
    __shared__ float sb;
    if (threadIdx.x < H) sw[threadIdx.x] = wp[threadIdx.x];
    if (threadIdx.x == 0) sb = bp[0];
    __syncthreads();
    int v = blockIdx.x * blockDim.x + threadIdx.x;
    if (v >= NV) return;
    const float4* hp = (const float4*)(buf + v * H);
    float a = sb;
#pragma unroll
    for (int k = 0; k < 4; k++) {
        float4 h4 = hp[k];
        a += h4.x * sw[4*k] + h4.y * sw[4*k+1] + h4.z * sw[4*k+2] + h4.w * sw[4*k+3];
    }
    out[v] = a;
}

// ---------------- launch ----------------
extern "C" void kernel_launch(void* const* d_in, const int* in_sizes, int n_in,
                              void* d_out, int out_size) {
    const float* x      = (const float*)d_in[0];
    const float* w_emb  = (const float*)d_in[1];
    const float* b_emb  = (const float*)d_in[2];
    const float* W1     = (const float*)d_in[3];
    const float* b1     = (const float*)d_in[4];
    const float* g1     = (const float*)d_in[5];
    const float* be1    = (const float*)d_in[6];
    const float* W2     = (const float*)d_in[7];
    const float* b2     = (const float*)d_in[8];
    const float* g2     = (const float*)d_in[9];
    const float* be2    = (const float*)d_in[10];
    const float* W3     = (const float*)d_in[11];
    const float* b3     = (const float*)d_in[12];
    const float* g3     = (const float*)d_in[13];
    const float* be3    = (const float*)d_in[14];
    const float* w_proj = (const float*)d_in[15];
    const float* b_proj = (const float*)d_in[16];

    float *bufA, *bufB, *bufC, *w1t, *w2t, *w3t;
    double *sums, *ssqs;
    cudaGetSymbolAddress((void**)&bufA, g_bufA);
    cudaGetSymbolAddress((void**)&bufB, g_bufB);
    cudaGetSymbolAddress((void**)&bufC, g_bufC);
    cudaGetSymbolAddress((void**)&w1t, g_W1t);
    cudaGetSymbolAddress((void**)&w2t, g_W2t);
    cudaGetSymbolAddress((void**)&w3t, g_W3t);
    cudaGetSymbolAddress((void**)&sums, g_sum);
    cudaGetSymbolAddress((void**)&ssqs, g_ssq);

    // smem: conv1 (1728+1600)*16 = 53248; conv2 (1728+3200)*16 = 78848; conv3 (3456+3200)*16 = 106496
    cudaFuncSetAttribute(conv4d_kernel<16, 16>, cudaFuncAttributeMaxDynamicSharedMemorySize, 53248);
    cudaFuncSetAttribute(conv4d_kernel<16, 32>, cudaFuncAttributeMaxDynamicSharedMemorySize, 78848);
    cudaFuncSetAttribute(conv4d_kernel<32, 16>, cudaFuncAttributeMaxDynamicSharedMemorySize, 106496);

    zero_stats_kernel<<<1, 128>>>(sums, ssqs);
    reorder_w_kernel<<<(625 * 16 * 16 + 255) / 256, 256>>>(W1, w1t, 16, 16);
    reorder_w_kernel<<<(625 * 16 * 32 + 255) / 256, 256>>>(W2, w2t, 16, 32);
    reorder_w_kernel<<<(625 * 32 * 16 + 255) / 256, 256>>>(W3, w3t, 32, 16);

    embed_kernel<<<NV / 256, 256>>>(x, w_emb, b_emb, bufA);

    const int CONV_GRID = B * D1 * D2 * (D3 / 8);  // 1024

    conv4d_kernel<16, 16><<<CONV_GRID, 128, 53248>>>(bufA, w1t, b1, bufB);
    bn_stats_kernel<16><<<512, 256>>>(bufB, sums + 0, ssqs + 0);
    bn_apply_kernel<16><<<1024, 256>>>(bufB, sums + 0, ssqs + 0, g1, be1);

    conv4d_kernel<16, 32><<<CONV_GRID, 256, 78848>>>(bufB, w2t, b2, bufC);
    bn_stats_kernel<32><<<512, 256>>>(bufC, sums + 32, ssqs + 32);
    bn_apply_kernel<32><<<1024, 256>>>(bufC, sums + 32, ssqs + 32, g2, be2);

    conv4d_kernel<32, 16><<<CONV_GRID, 128, 106496>>>(bufC, w3t, b3, bufA);
    bn_stats_kernel<16><<<512, 256>>>(bufA, sums + 64, ssqs + 64);
    bn_apply_kernel<16><<<1024, 256>>>(bufA, sums + 64, ssqs + 64, g3, be3);

    proj_kernel<<<NV / 256, 256>>>(bufA, w_proj, b_proj, (float*)d_out);
}